// round 3
// baseline (speedup 1.0000x reference)
#include <cuda_runtime.h>

#define IMG_H 2048
#define IMG_W 2048

constexpr int TX = 32;
constexpr int TY = 32;
constexpr int HALO = 3;

__global__ __launch_bounds__(256)
void plane_fit_kernel(const float* __restrict__ x, float* __restrict__ out) {
    __shared__ float in_s[TY + 6][TX + 6 + 2];  // 38 x 40 (pad to dodge conflicts)
    __shared__ float S_s [TY + 6][TX + 1];      // horizontal box sums
    __shared__ float D_s [TY + 6][TX + 1];      // horizontal gradient sums

    const int bx = blockIdx.x * TX;
    const int by = blockIdx.y * TY;
    const int tid = threadIdx.y * 32 + threadIdx.x;

    // ---- load padded tile (edge clamp == ReplicationPad2d) ----
    #pragma unroll
    for (int i = tid; i < (TY + 6) * (TX + 6); i += 256) {
        int r = i / (TX + 6);
        int c = i % (TX + 6);
        int gy = by + r - HALO;
        int gx = bx + c - HALO;
        gy = min(max(gy, 0), IMG_H - 1);
        gx = min(max(gx, 0), IMG_W - 1);
        in_s[r][c] = x[(size_t)gy * IMG_W + gx];
    }
    __syncthreads();

    // ---- horizontal pass: S = box7, D = sum (k-3)*v, for 38 rows x 32 cols ----
    #pragma unroll
    for (int i = tid; i < (TY + 6) * TX; i += 256) {
        int r = i / TX;
        int c = i % TX;
        float s = 0.0f, d = 0.0f;
        #pragma unroll
        for (int k = 0; k < 7; k++) {
            float v = in_s[r][c + k];
            s += v;
            d += (float)(k - 3) * v;
        }
        S_s[r][c] = s;
        D_s[r][c] = d;
    }
    __syncthreads();

    // ---- vertical pass: each thread handles 4 output rows ----
    const int lx = threadIdx.x;
    #pragma unroll
    for (int r0 = threadIdx.y; r0 < TY; r0 += 8) {
        float sS = 0.0f, sD = 0.0f, sY = 0.0f;
        #pragma unroll
        for (int k = 0; k < 7; k++) {
            float s = S_s[r0 + k][lx];
            sS += s;
            sY += (float)(k - 3) * s;
            sD += D_s[r0 + k][lx];
        }
        const int gy = by + r0;
        const int gx = bx + lx;
        size_t o = ((size_t)gy * IMG_W + gx) * 3;
        out[o + 0] = sD * (1.0f / 196.0f);  // C0: x-slope
        out[o + 1] = sY * (1.0f / 196.0f);  // C1: y-slope
        out[o + 2] = sS * (1.0f / 49.0f);   // C2: mean
    }
}

extern "C" void kernel_launch(void* const* d_in, const int* in_sizes, int n_in,
                              void* d_out, int out_size) {
    const float* x = (const float*)d_in[0];
    float* out = (float*)d_out;
    dim3 block(32, 8);
    dim3 grid(IMG_W / TX, IMG_H / TY);
    plane_fit_kernel<<<grid, block>>>(x, out);
}

// round 4
// speedup vs baseline: 1.0898x; 1.0898x over previous
#include <cuda_runtime.h>

#define IMG_H 2048
#define IMG_W 2048

constexpr int TX = 32;
constexpr int TY = 32;

__global__ __launch_bounds__(256, 8)
void plane_fit_kernel(const float* __restrict__ x, float* __restrict__ out) {
    __shared__ __align__(16) float in_s[38][40];   // padded input tile
    __shared__ __align__(16) float S_s [38][33];   // horizontal box sums
    __shared__ __align__(16) float D_s [38][33];   // horizontal gradient sums
    __shared__ __align__(16) float out_s[TY][100]; // 96 floats/row + pad (400B = 25*16B)

    const int bx = blockIdx.x * TX;
    const int by = blockIdx.y * TY;
    const int tx = threadIdx.x;   // 0..31
    const int ty = threadIdx.y;   // 0..7
    const int tid = ty * 32 + tx;

    // ---- load padded 38x38 tile (edge clamp == ReplicationPad2d) ----
    #pragma unroll
    for (int r = ty; r < 38; r += 8) {
        #pragma unroll
        for (int c = tx; c < 38; c += 32) {
            int gy = min(max(by + r - 3, 0), IMG_H - 1);
            int gx = min(max(bx + c - 3, 0), IMG_W - 1);
            in_s[r][c] = x[(size_t)gy * IMG_W + gx];
        }
    }
    __syncthreads();

    // ---- horizontal pass: 38 rows x 32 cols ----
    #pragma unroll
    for (int r = ty; r < 38; r += 8) {
        float s = 0.0f, d = 0.0f;
        #pragma unroll
        for (int k = 0; k < 7; k++) {
            float v = in_s[r][tx + k];
            s += v;
            d += (float)(k - 3) * v;
        }
        S_s[r][tx] = s;
        D_s[r][tx] = d;
    }
    __syncthreads();

    // ---- vertical pass: sliding window in registers, 4 rows per thread ----
    {
        const int rbase = ty * 4;
        float S[10], D[10];
        #pragma unroll
        for (int k = 0; k < 10; k++) {
            S[k] = S_s[rbase + k][tx];
            D[k] = D_s[rbase + k][tx];
        }
        #pragma unroll
        for (int r = 0; r < 4; r++) {
            float sS = 0.0f, sY = 0.0f, sD = 0.0f;
            #pragma unroll
            for (int k = 0; k < 7; k++) {
                float s = S[r + k];
                sS += s;
                sY += (float)(k - 3) * s;
                sD += D[r + k];
            }
            // stride-3 column writes: 3 coprime to 32 -> conflict-free
            out_s[rbase + r][tx * 3 + 0] = sD * (1.0f / 196.0f); // C0: x-slope
            out_s[rbase + r][tx * 3 + 1] = sY * (1.0f / 196.0f); // C1: y-slope
            out_s[rbase + r][tx * 3 + 2] = sS * (1.0f / 49.0f);  // C2: mean
        }
    }
    __syncthreads();

    // ---- coalesced float4 stores: 32 rows x 24 float4 = 768, 3 per thread ----
    #pragma unroll
    for (int i = tid; i < 32 * 24; i += 256) {
        int r  = i / 24;
        int c4 = i % 24;
        float4 v = *reinterpret_cast<const float4*>(&out_s[r][c4 * 4]);
        size_t o = ((size_t)(by + r) * IMG_W + bx) * 3 + (size_t)c4 * 4;
        *reinterpret_cast<float4*>(&out[o]) = v;
    }
}

extern "C" void kernel_launch(void* const* d_in, const int* in_sizes, int n_in,
                              void* d_out, int out_size) {
    const float* x = (const float*)d_in[0];
    float* out = (float*)d_out;
    dim3 block(32, 8);
    dim3 grid(IMG_W / TX, IMG_H / TY);
    plane_fit_kernel<<<grid, block>>>(x, out);
}

// round 5
// speedup vs baseline: 1.1140x; 1.0223x over previous
#include <cuda_runtime.h>

#define IMG_H 2048
#define IMG_W 2048

constexpr int TW = 128;  // tile width  (32 threads x 4 cols)
constexpr int TH = 32;   // tile height (8 thread-rows x 4 rows)

__global__ __launch_bounds__(256)
void plane_fit_kernel(const float* __restrict__ x, float* __restrict__ out) {
    __shared__ __align__(16) float Ssh[38][132];  // horizontal box sums  (row stride 132 floats)
    __shared__ __align__(16) float Dsh[38][132];  // horizontal gradient sums

    const int cx  = threadIdx.x;          // 0..31 -> 4-column group
    const int ty  = threadIdx.y;          // 0..7
    const int bx0 = blockIdx.x * TW;
    const int by0 = blockIdx.y * TH;
    const int gx0 = bx0 + 4 * cx;         // first of this thread's 4 output columns

    // ================= Phase 1: horizontal pass =================
    // For input rows j = 0..37 (tile rows -3..34, row-clamped), compute
    // S(c) = sum_{k=-3..3} v(c+k), D(c) = sum_{k} k*v(c+k) for 4 columns.
    const bool interior = (gx0 - 4 >= 0) && (gx0 + 7 <= IMG_W - 1);

    for (int j = ty; j < 38; j += 8) {
        const int gy = min(max(by0 + j - 3, 0), IMG_H - 1);
        const float* __restrict__ row = x + (size_t)gy * IMG_W;

        float f[12];  // input cols gx0-4 .. gx0+7
        if (interior) {
            float4 a = *reinterpret_cast<const float4*>(row + gx0 - 4);
            float4 b = *reinterpret_cast<const float4*>(row + gx0);
            float4 c = *reinterpret_cast<const float4*>(row + gx0 + 4);
            f[0]=a.x; f[1]=a.y; f[2]=a.z;  f[3]=a.w;
            f[4]=b.x; f[5]=b.y; f[6]=b.z;  f[7]=b.w;
            f[8]=c.x; f[9]=c.y; f[10]=c.z; f[11]=c.w;
        } else {
            #pragma unroll
            for (int m = 0; m < 12; m++) {
                int gc = min(max(gx0 - 4 + m, 0), IMG_W - 1);
                f[m] = row[gc];
            }
        }

        // sliding sums: S(c) over f[c+1..c+7], D(c) = sum (t-4-c)*f[t]
        float S0 = f[1]+f[2]+f[3]+f[4]+f[5]+f[6]+f[7];
        float S1 = S0 - f[1] + f[8];
        float S2 = S1 - f[2] + f[9];
        float S3 = S2 - f[3] + f[10];
        float D0 = -3.0f*f[1] - 2.0f*f[2] - f[3] + f[5] + 2.0f*f[6] + 3.0f*f[7];
        float D1 = D0 + 3.0f*f[1] + 4.0f*f[8]  - S1;
        float D2 = D1 + 3.0f*f[2] + 4.0f*f[9]  - S2;
        float D3 = D2 + 3.0f*f[3] + 4.0f*f[10] - S3;

        *reinterpret_cast<float4*>(&Ssh[j][4*cx]) = make_float4(S0, S1, S2, S3);
        *reinterpret_cast<float4*>(&Dsh[j][4*cx]) = make_float4(D0, D1, D2, D3);
    }
    __syncthreads();

    // ================= Phase 2: vertical pass =================
    // Thread handles output rows ty*4..ty*4+3, cols gx0..gx0+3.
    // Stream 10 S/D rows, accumulate 3 sums x 4 rows x float4.
    const int r0 = ty * 4;
    float4 sS[4], sY[4], sD[4];
    #pragma unroll
    for (int ri = 0; ri < 4; ri++) {
        sS[ri] = make_float4(0.f,0.f,0.f,0.f);
        sY[ri] = make_float4(0.f,0.f,0.f,0.f);
        sD[ri] = make_float4(0.f,0.f,0.f,0.f);
    }

    #pragma unroll
    for (int j = 0; j < 10; j++) {
        float4 Sj = *reinterpret_cast<const float4*>(&Ssh[r0 + j][4*cx]);
        float4 Dj = *reinterpret_cast<const float4*>(&Dsh[r0 + j][4*cx]);
        #pragma unroll
        for (int ri = 0; ri < 4; ri++) {
            const int k = j - ri;          // kernel row 0..6
            if (k >= 0 && k < 7) {
                const float w = (float)(k - 3);
                sS[ri].x += Sj.x; sS[ri].y += Sj.y; sS[ri].z += Sj.z; sS[ri].w += Sj.w;
                sY[ri].x += w*Sj.x; sY[ri].y += w*Sj.y; sY[ri].z += w*Sj.z; sY[ri].w += w*Sj.w;
                sD[ri].x += Dj.x; sD[ri].y += Dj.y; sD[ri].z += Dj.z; sD[ri].w += Dj.w;
            }
        }
    }

    // ================= Stores: 3 coalesced float4 per output row =================
    const float inv196 = 1.0f / 196.0f;
    const float inv49  = 1.0f / 49.0f;
    #pragma unroll
    for (int ri = 0; ri < 4; ri++) {
        const int gy = by0 + r0 + ri;
        float* __restrict__ o = out + ((size_t)gy * IMG_W + gx0) * 3;
        float4 p0 = make_float4(sD[ri].x*inv196, sY[ri].x*inv196, sS[ri].x*inv49,
                                sD[ri].y*inv196);
        float4 p1 = make_float4(sY[ri].y*inv196, sS[ri].y*inv49,
                                sD[ri].z*inv196, sY[ri].z*inv196);
        float4 p2 = make_float4(sS[ri].z*inv49,
                                sD[ri].w*inv196, sY[ri].w*inv196, sS[ri].w*inv49);
        reinterpret_cast<float4*>(o)[0] = p0;
        reinterpret_cast<float4*>(o)[1] = p1;
        reinterpret_cast<float4*>(o)[2] = p2;
    }
}

extern "C" void kernel_launch(void* const* d_in, const int* in_sizes, int n_in,
                              void* d_out, int out_size) {
    const float* x = (const float*)d_in[0];
    float* out = (float*)d_out;
    dim3 block(32, 8);
    dim3 grid(IMG_W / TW, IMG_H / TH);
    plane_fit_kernel<<<grid, block>>>(x, out);
}